// round 16
// baseline (speedup 1.0000x reference)
#include <cuda_runtime.h>

#define B_    256
#define T_    1024
#define NUM_  126
#define L_    128
#define HOFF  68     // float offset of half-1 reads (272B) -> disjoint bank groups
#define PBUF  136

__device__ int d_perm[B_];

// Rank-sort sequences by length (descending), deterministic, O(n^2) with n=256.
__global__ void crf_sort_kernel(const int* __restrict__ lens){
    __shared__ int sl[B_];
    int i = threadIdx.x;
    sl[i] = lens[i];
    __syncthreads();
    int v = sl[i];
    int r = 0;
    #pragma unroll 8
    for (int j = 0; j < B_; j++){
        int w = sl[j];
        r += (int)((w > v) | ((w == v) & (j < i)));
    }
    d_perm[r] = i;
}

__device__ __forceinline__ void ffma2(unsigned long long &d, unsigned long long a, unsigned long long b){
    asm volatile("fma.rn.f32x2 %0, %1, %2, %0;" : "+l"(d) : "l"(a), "l"(b));
}
__device__ __forceinline__ unsigned long long fadd2(unsigned long long a, unsigned long long b){
    unsigned long long d;
    asm volatile("add.rn.f32x2 %0, %1, %2;" : "=l"(d) : "l"(a), "l"(b));
    return d;
}
// Warp max of a NON-NEGATIVE float (bits are s32-monotonic).
__device__ __forceinline__ float redux_max_pos(float v){
    int r;
    asm volatile("redux.sync.max.s32 %0, %1, 0xffffffff;" : "=r"(r) : "r"(__float_as_int(v)));
    return __int_as_float(r);
}
__device__ __forceinline__ float blockmax8(const float* red){
    float4 ra = *(const float4*)red;
    float4 rb = *(const float4*)(red + 4);
    return fmaxf(fmaxf(fmaxf(ra.x, ra.y), fmaxf(ra.z, ra.w)),
                 fmaxf(fmaxf(rb.x, rb.y), fmaxf(rb.z, rb.w)));
}

// Half dot: s = sum_{i<64} E[i]*p[i]; E = 32 packed f32x2 regs; p broadcast per half
// (even lanes one address, odd lanes one address at +272B -> disjoint bank groups).
__device__ __forceinline__ float dot64(const float* __restrict__ p, const unsigned long long* __restrict__ E){
    const ulonglong2* pd = (const ulonglong2*)p;   // 16 x 16B
    unsigned long long a0 = 0ull, a1 = 0ull, a2 = 0ull, a3 = 0ull;
    #pragma unroll
    for (int i = 0; i < 16; i += 2){
        ulonglong2 q0 = pd[i];
        ulonglong2 q1 = pd[i + 1];
        ffma2(a0, E[2*i + 0], q0.x);
        ffma2(a1, E[2*i + 1], q0.y);
        ffma2(a2, E[2*i + 2], q1.x);
        ffma2(a3, E[2*i + 3], q1.y);
    }
    unsigned long long s2 = fadd2(fadd2(a0, a1), fadd2(a2, a3));
    return __uint_as_float((unsigned)(s2 & 0xffffffffull)) +
           __uint_as_float((unsigned)(s2 >> 32));
}

#define GBAR(id) asm volatile("bar.sync %0, 256;" :: "r"(id) : "memory")

__global__ void __launch_bounds__(512, 1)
crf_main_kernel(const float* __restrict__ logits,
                const int*   __restrict__ labels,
                const int*   __restrict__ lens,
                const float* __restrict__ trans,
                float*       __restrict__ out)
{
    __shared__ __align__(16) float pb_all[2][2][PBUF];   // [group][parity][slot]
    __shared__ __align__(16) float red_all[2][2][8];     // [group][parity][warp-in-group]
    __shared__ float scal[2];
    __shared__ float redS[16], redG[16];

    const int tid  = threadIdx.x;
    const int grp  = tid >> 8;         // 0 = forward, 1 = backward
    const int gt   = tid & 255;        // thread in group
    const int j    = gt >> 1;          // label owned by lane pair
    const int half = gt & 1;           // 0: i in [0,64), 1: i in [64,128)
    const int lane = tid & 31;
    const int wg   = gt >> 5;          // warp in group (0..7)
    const int w16  = tid >> 5;         // warp in CTA

    const int seq = d_perm[blockIdx.x];   // rank = bid (descending length)
    const int len = lens[seq];
    const int m   = len >> 1;             // forward steps
    const int K   = len - m;              // backward matvecs (>=1)

    float (*pb)[PBUF] = pb_all[grp];
    float (*red)[8]   = red_all[grp];
    const int sj = j + ((j >= 64) ? 4 : 0);   // write slot, hoisted

    // ---- E half in 32 packed f32x2 regs ----
    // fwd: exp(Tr[j, 64h .. 64h+64));  bwd (transposed): exp(Tr[64h + i, j])
    unsigned long long E[32];
    #pragma unroll
    for (int q = 0; q < 32; q++){
        int i0 = half * 64 + 2 * q;
        float e0, e1;
        if (grp == 0){
            e0 = expf(trans[j * L_ + i0]);
            e1 = expf(trans[j * L_ + i0 + 1]);
        } else {
            e0 = expf(trans[(i0    ) * L_ + j]);
            e1 = expf(trans[(i0 + 1) * L_ + j]);
        }
        E[q] = (unsigned long long)__float_as_uint(e0)
             | ((unsigned long long)__float_as_uint(e1) << 32);
    }

    const float* lgp = logits + (size_t)seq * T_ * NUM_;

    // ---- gold score partial (512 threads stride over time) ----
    float gpart = 0.f;
    {
        const int* lab = labels + seq * T_;
        for (int t = tid; t < len; t += 512){
            int l1 = lab[t];
            gpart += lgp[(size_t)t * NUM_ + l1];
            int l0 = (t == 0) ? (L_ - 2) : lab[t - 1];
            gpart += trans[l1 * L_ + l0];
        }
        if (tid == 0) gpart += trans[(L_ - 1) * L_ + lab[len - 1]];
    }

    const bool ok = (j < NUM_);
    float c = 0.f, r = 1.f, Mcur = 1.f;
    float ubuf[4];

    const float* rd0 = pb[0] + half * HOFF;   // read base, parity 0
    const float* rd1 = pb[1] + half * HOFF;   // read base, parity 1

    if (grp == 0){
        // ================= FORWARD: a <- u_t * (E a), t = 0..m-1 =================
        if (!half) pb[0][sj] = (j == (L_ - 2)) ? 1.f : 0.f;
        GBAR(1);
        #pragma unroll
        for (int k = 0; k < 4; k++)
            ubuf[k] = ok ? __expf(__ldg(lgp + (size_t)k * NUM_ + j)) : 0.f;

        int t0 = 0;
        while (t0 + 4 <= m){
            float nlg[4];
            #pragma unroll
            for (int k = 0; k < 4; k++){
                int tp = t0 + 4 + k;
                nlg[k] = (ok && tp < T_) ? __ldg(lgp + (size_t)tp * NUM_ + j) : -1.0e30f;
            }
            #pragma unroll
            for (int k = 0; k < 4; k++){
                // t = t0 + k; t&1 == k&1 (t0 multiple of 4) -> static parity
                float s = dot64((k & 1) ? rd1 : rd0, E);
                s += __shfl_xor_sync(0xffffffffu, s, 1);   // combine halves
                float v = s * ubuf[k] * r;                 // stale renorm scale
                float Mw = redux_max_pos(v);
                if (lane == 0) red[k & 1][wg] = Mw;
                if (!half) pb[(k & 1) ^ 1][sj] = v;
                GBAR(1);
                Mcur = blockmax8(red[k & 1]);
                r = __fdividef(1.f, Mcur);
                c += __logf(Mcur);
            }
            #pragma unroll
            for (int k = 0; k < 4; k++) ubuf[k] = __expf(nlg[k]);
            t0 += 4;
        }
        #pragma unroll
        for (int k = 0; k < 3; k++){
            if (t0 + k < m){
                float s = dot64((k & 1) ? rd1 : rd0, E);
                s += __shfl_xor_sync(0xffffffffu, s, 1);
                float v = s * ubuf[k] * r;
                float Mw = redux_max_pos(v);
                if (lane == 0) red[k & 1][wg] = Mw;
                if (!half) pb[(k & 1) ^ 1][sj] = v;
                GBAR(1);
                Mcur = blockmax8(red[k & 1]);
                r = __fdividef(1.f, Mcur);
                c += __logf(Mcur);
            }
        }
        if (gt == 0) scal[0] = c - __logf(Mcur);           // m==0 -> 0
    } else {
        // ================= BACKWARD: b <- E^T (u_t * b), matvecs k = 1..K =================
        float wj = __expf(trans[(L_ - 1) * L_ + j]);
        float ul = ok ? __expf(__ldg(lgp + (size_t)(len - 1) * NUM_ + j)) : 0.f;
        float v0 = ul * wj;
        float Mw0 = redux_max_pos(v0);
        if (lane == 0) red[0][wg] = Mw0;
        if (!half) pb[0][sj] = v0;
        GBAR(2);
        Mcur = blockmax8(red[0]);
        r = __fdividef(1.f, Mcur);
        c = __logf(Mcur);

        // ubuf[kk] = u for matvec k0+kk; matvec K uses u=1 (no emission on that hop).
        #pragma unroll
        for (int kk = 0; kk < 4; kk++){
            int k = 1 + kk;
            ubuf[kk] = (k == K) ? 1.f
                     : ((k < K && ok) ? __expf(__ldg(lgp + (size_t)(len - 1 - k) * NUM_ + j)) : 0.f);
        }

        int k0 = 1;
        while (k0 + 3 <= K){
            float nlg[4];
            #pragma unroll
            for (int kk = 0; kk < 4; kk++){
                int kp = k0 + 4 + kk;
                nlg[kk] = (kp < K && ok) ? __ldg(lgp + (size_t)(len - 1 - kp) * NUM_ + j) : -1.0e30f;
            }
            #pragma unroll
            for (int kk = 0; kk < 4; kk++){
                // k = k0 + kk; k&1 == (1+kk)&1 -> static; read parity (k&1)^1, write k&1
                const int wpar = (kk + 1) & 1;             // == k&1
                float s = dot64(wpar ? rd0 : rd1, E);      // read (k&1)^1
                s += __shfl_xor_sync(0xffffffffu, s, 1);
                float v = s * r * ubuf[kk];
                float Mw = redux_max_pos(v);
                if (lane == 0) red[wpar][wg] = Mw;
                if (!half) pb[wpar][sj] = v;
                GBAR(2);
                Mcur = blockmax8(red[wpar]);
                r = __fdividef(1.f, Mcur);
                c += __logf(Mcur);
            }
            #pragma unroll
            for (int kk = 0; kk < 4; kk++){
                int kn = k0 + 4 + kk;
                ubuf[kk] = (kn == K) ? 1.f : __expf(nlg[kk]);
            }
            k0 += 4;
        }
        #pragma unroll
        for (int kk = 0; kk < 3; kk++){
            if (k0 + kk <= K){
                const int wpar = (kk + 1) & 1;
                float s = dot64(wpar ? rd0 : rd1, E);
                s += __shfl_xor_sync(0xffffffffu, s, 1);
                float v = s * r * ubuf[kk];
                float Mw = redux_max_pos(v);
                if (lane == 0) red[wpar][wg] = Mw;
                if (!half) pb[wpar][sj] = v;
                GBAR(2);
                Mcur = blockmax8(red[wpar]);
                r = __fdividef(1.f, Mcur);
                c += __logf(Mcur);
            }
        }
        if (gt == 0) scal[1] = c - __logf(Mcur);
    }

    // ================= merge: norm = log(sum_j a[j]*b[j]) + cf' + cb' =================
    __syncthreads();
    const float* A  = pb_all[0][m & 1];
    const float* Bv = pb_all[1][K & 1];
    float prod = 0.f;
    if (tid < L_){
        int st = tid + ((tid >= 64) ? 4 : 0);
        prod = A[st] * Bv[st];
    }
    #pragma unroll
    for (int o = 16; o; o >>= 1){
        prod  += __shfl_xor_sync(0xffffffffu, prod,  o);
        gpart += __shfl_xor_sync(0xffffffffu, gpart, o);
    }
    if (lane == 0){ redS[w16] = prod; redG[w16] = gpart; }
    __syncthreads();
    if (tid == 0){
        float S = 0.f, G = 0.f;
        #pragma unroll
        for (int i = 0; i < 16; i++){ S += redS[i]; G += redG[i]; }
        out[seq] = G - (__logf(S) + scal[0] + scal[1]);
    }
}

extern "C" void kernel_launch(void* const* d_in, const int* in_sizes, int n_in,
                              void* d_out, int out_size)
{
    (void)in_sizes; (void)n_in; (void)out_size;
    const float* logits = (const float*)d_in[0];
    const int*   labels = (const int*)d_in[1];
    const int*   lens   = (const int*)d_in[2];
    const float* trans  = (const float*)d_in[3];
    float*       out    = (float*)d_out;

    crf_sort_kernel<<<1, B_>>>(lens);
    crf_main_kernel<<<B_, 512>>>(logits, labels, lens, trans, out);
}